// round 4
// baseline (speedup 1.0000x reference)
#include <cuda_runtime.h>
#include <math.h>
#include <stdint.h>

#define S_DIM 32
#define A_DIM 4
#define F1    36     // S+A
#define H1    64
#define F2    7      // A+3
#define H2    32
#define MAXK  16384

// ---------------- scratch (allocation-free: __device__ globals) ----------------
__device__ float g_cnt[MAXK];
__device__ __align__(16) float g_sumA[MAXK * A_DIM];
__device__ __align__(16) float g_ssq[MAXK * A_DIM];
__device__ float g_sumS[MAXK];
__device__ float g_sume[MAXK];
__device__ __align__(16) float g_sumeA[MAXK * A_DIM];
__device__ float g_impc[MAXK];

// ---------------- packed f32x2 helpers (Blackwell sm_100+) ----------------
#define PACK2(out, lo, hi) \
    asm("mov.b64 %0, {%1, %2};" : "=l"(out) : "f"(lo), "f"(hi))
#define UNPACK2(lo, hi, v) \
    asm("mov.b64 {%0, %1}, %2;" : "=f"(lo), "=f"(hi) : "l"(v))
#define FMA2(d, a, b, c) \
    asm("fma.rn.f32x2 %0, %1, %2, %3;" : "=l"(d) : "l"(a), "l"(b), "l"(c))

// ---------------- warp segmented sum (seg_ids sorted => contiguous groups) ----
__device__ __forceinline__ float segSum(float v, int rel, int sz) {
#pragma unroll
    for (int off = 16; off > 0; off >>= 1) {
        float t = __shfl_down_sync(0xffffffffu, v, off);
        if (rel + off < sz) v += t;
    }
    return v;
}

// ---------------- kernel 0: zero accumulators ----------------
__global__ void zeroK(int K) {
    int k = blockIdx.x * blockDim.x + threadIdx.x;
    if (k < K) {
        g_cnt[k] = 0.f;
        g_sumS[k] = 0.f;
        g_sume[k] = 0.f;
#pragma unroll
        for (int a = 0; a < A_DIM; a++) {
            g_sumA[k * A_DIM + a] = 0.f;
            g_ssq[k * A_DIM + a] = 0.f;
            g_sumeA[k * A_DIM + a] = 0.f;
        }
    }
}

// ---------------- pass A: fused per-cell MLP (f32x2) + all segmented accumulators ----
__global__ void __launch_bounds__(256) passA(
    const float* __restrict__ state, const float* __restrict__ arch,
    const float* __restrict__ energy, const float* __restrict__ phi_local,
    const float* __restrict__ surprise, const int* __restrict__ seg_ids,
    const float* __restrict__ W1, const float* __restrict__ b1,
    const float* __restrict__ W2, const float* __restrict__ b2, int N)
{
    // Per hidden unit j: 18 weight PAIRS over the feature dim, slot 18 = (bias, 0).
    // Stride 20 pairs (160B) keeps 16B alignment for ulonglong2 loads.
    __shared__ __align__(16) float2 s_w1p[H1 * 20];
    __shared__ float s_w2[H1];
    __shared__ float s_b2;
    int t = threadIdx.x;
    for (int idx = t; idx < H1 * 18; idx += 256) {
        int j = idx / 18, q = idx % 18;     // W1 is [36,64] row-major: W1[i*64+j]
        s_w1p[j * 20 + q] = make_float2(W1[(2 * q) * H1 + j], W1[(2 * q + 1) * H1 + j]);
    }
    if (t < H1) {
        s_w1p[t * 20 + 18] = make_float2(b1[t], 0.f);
        s_w2[t] = W2[t];
        if (t == 0) s_b2 = b2[0];
    }
    __syncthreads();

    int cell = blockIdx.x * 256 + t;
    bool active = cell < N;
    int cc = active ? cell : (N - 1);

    // Load + pack features into 18 b64 pairs
    unsigned long long fp[18];
    const float4* sp = reinterpret_cast<const float4*>(state + (size_t)cc * S_DIM);
#pragma unroll
    for (int q = 0; q < 8; q++) {
        float4 v = sp[q];
        PACK2(fp[2 * q + 0], v.x, v.y);
        PACK2(fp[2 * q + 1], v.z, v.w);
    }
    float4 av = *reinterpret_cast<const float4*>(arch + (size_t)cc * A_DIM);
    PACK2(fp[16], av.x, av.y);
    PACK2(fp[17], av.z, av.w);

    float acc = 0.f;
#pragma unroll 4
    for (int j = 0; j < H1; j++) {
        const ulonglong2* wr = reinterpret_cast<const ulonglong2*>(s_w1p + j * 20);
        // init accumulator pair with (bias, 0)
        unsigned long long acc2 =
            reinterpret_cast<const unsigned long long*>(s_w1p + j * 20)[18];
#pragma unroll
        for (int q2 = 0; q2 < 9; q2++) {
            ulonglong2 wv = wr[q2];
            FMA2(acc2, fp[2 * q2 + 0], wv.x, acc2);
            FMA2(acc2, fp[2 * q2 + 1], wv.y, acc2);
        }
        float lo, hi;
        UNPACK2(lo, hi, acc2);
        acc = fmaf(fmaxf(lo + hi, 0.f), s_w2[j], acc);
    }

    float ep   = energy[cc] * phi_local[cc];
    float base = 1.f / (1.f + expf(-(acc + s_b2)));
    float imp  = fminf(fmaxf(base * ep, 0.01f), 1.f);
    float w    = imp * ep;                   // w in (0, 1]
    float e    = expf(w);                    // exp in (1, e]; softmax ratios identical

    int seg = seg_ids[cc];
    float sa0 = active ? av.x : 0.f, sa1 = active ? av.y : 0.f;
    float sa2 = active ? av.z : 0.f, sa3 = active ? av.w : 0.f;
    float q0 = sa0 * av.x, q1 = sa1 * av.y, q2 = sa2 * av.z, q3 = sa3 * av.w;
    float su = active ? surprise[cc] : 0.f;
    float ev = active ? e : 0.f;
    float e0 = ev * av.x, e1 = ev * av.y, e2 = ev * av.z, e3 = ev * av.w;

    int lane = t & 31;
    unsigned actm  = __ballot_sync(0xffffffffu, active);
    unsigned peers = __match_any_sync(0xffffffffu, seg);
    int leader = __ffs(peers) - 1;
    int rel = lane - leader;
    int sz  = __popc(peers);
    float one = (float)__popc(peers & actm);   // count: no shuffle chain needed

    sa0 = segSum(sa0, rel, sz); sa1 = segSum(sa1, rel, sz);
    sa2 = segSum(sa2, rel, sz); sa3 = segSum(sa3, rel, sz);
    q0  = segSum(q0, rel, sz);  q1  = segSum(q1, rel, sz);
    q2  = segSum(q2, rel, sz);  q3  = segSum(q3, rel, sz);
    su  = segSum(su, rel, sz);
    ev  = segSum(ev, rel, sz);
    e0  = segSum(e0, rel, sz);  e1  = segSum(e1, rel, sz);
    e2  = segSum(e2, rel, sz);  e3  = segSum(e3, rel, sz);

    if (lane == leader) {
        atomicAdd(&g_cnt[seg], one);
        atomicAdd(&g_sumA[seg * 4 + 0], sa0);
        atomicAdd(&g_sumA[seg * 4 + 1], sa1);
        atomicAdd(&g_sumA[seg * 4 + 2], sa2);
        atomicAdd(&g_sumA[seg * 4 + 3], sa3);
        atomicAdd(&g_ssq[seg * 4 + 0], q0);
        atomicAdd(&g_ssq[seg * 4 + 1], q1);
        atomicAdd(&g_ssq[seg * 4 + 2], q2);
        atomicAdd(&g_ssq[seg * 4 + 3], q3);
        atomicAdd(&g_sumS[seg], su);
        atomicAdd(&g_sume[seg], ev);
        atomicAdd(&g_sumeA[seg * 4 + 0], e0);
        atomicAdd(&g_sumeA[seg * 4 + 1], e1);
        atomicAdd(&g_sumeA[seg * 4 + 2], e2);
        atomicAdd(&g_sumeA[seg * 4 + 3], e3);
    }
}

// ---------------- pass C: per-cluster finalize + cluster MLP ----------------
__global__ void __launch_bounds__(256) passC(
    const float* __restrict__ V1, const float* __restrict__ c1,
    const float* __restrict__ V2, const float* __restrict__ c2,
    float* __restrict__ out, int K)
{
    __shared__ float s_v1t[H2 * F2];   // [j][i]
    __shared__ float s_c1[H2], s_v2[H2];
    __shared__ float s_c2;
    int t = threadIdx.x;
    if (t < F2 * H2) {                 // V1 is [7,32] row-major
        int i = t / H2, j = t % H2;
        s_v1t[j * F2 + i] = V1[t];
    }
    if (t < H2) { s_c1[t] = c1[t]; s_v2[t] = V2[t]; }
    if (t == 0) s_c2 = c2[0];
    __syncthreads();

    int k = blockIdx.x * 256 + t;
    if (k >= K) return;

    float cntr = g_cnt[k];
    bool valid = cntr > 0.f;
    float se = g_sume[k];

    float4 seA = *reinterpret_cast<const float4*>(&g_sumeA[k * 4]);
    float4 sA  = *reinterpret_cast<const float4*>(&g_sumA[k * 4]);
    float4 sQ  = *reinterpret_cast<const float4*>(&g_ssq[k * 4]);

    float agg[A_DIM];
    agg[0] = valid ? seA.x / se : 0.f;
    agg[1] = valid ? seA.y / se : 0.f;
    agg[2] = valid ? seA.z / se : 0.f;
    agg[3] = valid ? seA.w / se : 0.f;

    float mA = fmaxf(fmaxf(agg[0], agg[1]), fmaxf(agg[2], agg[3]));
    float ea[A_DIM], esum = 0.f;
#pragma unroll
    for (int a = 0; a < A_DIM; a++) { ea[a] = expf(agg[a] - mA); esum += ea[a]; }
    float aggr[A_DIM];
#pragma unroll
    for (int a = 0; a < A_DIM; a++) aggr[a] = ea[a] / esum;

    float cntc = fmaxf(cntr, 1.f);
    float dv   = fmaxf(cntr - 1.f, 1.f);
    float sAr[A_DIM] = { sA.x, sA.y, sA.z, sA.w };
    float sQr[A_DIM] = { sQ.x, sQ.y, sQ.z, sQ.w };
    float varsum = 0.f;
#pragma unroll
    for (int a = 0; a < A_DIM; a++) {
        float mean = sAr[a] / cntc;
        varsum += (sQr[a] - cntr * mean * mean) / dv;
    }
    float var_m   = varsum * 0.25f;
    float phi_c   = 1.f - fminf(1.f, var_m * 2.f);
    float coh     = 1.f - var_m;
    float pred_err = g_sumS[k] / cntc;
    float integ   = phi_c * (1.f - pred_err);

    float cfeat[F2] = { aggr[0], aggr[1], aggr[2], aggr[3],
                        phi_c, coh, fminf(1.f, cntr * (1.f / 20.f)) };
    float acc = 0.f;
#pragma unroll
    for (int j = 0; j < H2; j++) {
        float h = s_c1[j];
#pragma unroll
        for (int i = 0; i < F2; i++) h = fmaf(cfeat[i], s_v1t[j * F2 + i], h);
        acc = fmaf(fmaxf(h, 0.f), s_v2[j], acc);
    }
    float basec = 1.f / (1.f + expf(-(acc + s_c2)));
    float impc  = fminf(fmaxf(basec * phi_c, 0.01f), 1.f);

    float* row = out + (size_t)k * 8;
    row[0] = aggr[0]; row[1] = aggr[1]; row[2] = aggr[2]; row[3] = aggr[3];
    row[4] = phi_c; row[5] = coh; row[6] = pred_err; row[7] = integ;

    g_impc[k] = valid ? impc : -INFINITY;
}

// ---------------- finalize: single-pass (impc clipped to [0.01,1] => no max needed) ----
__device__ __forceinline__ float warpSum(float v) {
#pragma unroll
    for (int off = 16; off > 0; off >>= 1)
        v += __shfl_down_sync(0xffffffffu, v, off);
    return v;
}

__global__ void __launch_bounds__(1024) finalize(float* __restrict__ out, int K) {
    __shared__ float sp[32][9];
    __shared__ int   si[32];
    int t = threadIdx.x, lane = t & 31, wid = t >> 5;

    float nv = 0.f, se = 0.f, ga0 = 0.f, ga1 = 0.f, ga2 = 0.f, ga3 = 0.f;
    float sphi = 0.f, scoh = 0.f;
    int mask = 0;
    for (int k = t; k < K; k += 1024) {
        float ic = g_impc[k];
        const float4* r = reinterpret_cast<const float4*>(out + (size_t)k * 8);
        float4 a = r[0];
        float4 m = r[1];                 // phi_c, coh, pred_err, integ
        float u = expf(ic);              // exp(-inf) = 0 for invalid; impc<=1 so stable
        se += u;
        ga0 += u * a.x; ga1 += u * a.y; ga2 += u * a.z; ga3 += u * a.w;
        if (ic != -INFINITY) {
            nv += 1.f; sphi += m.x; scoh += m.y;
            int spec = 0; float bm = a.x;
            if (a.y > bm) { bm = a.y; spec = 1; }
            if (a.z > bm) { bm = a.z; spec = 2; }
            if (a.w > bm) { bm = a.w; spec = 3; }
            mask |= 1 << spec;
        }
    }
    nv = warpSum(nv); se = warpSum(se);
    ga0 = warpSum(ga0); ga1 = warpSum(ga1); ga2 = warpSum(ga2); ga3 = warpSum(ga3);
    sphi = warpSum(sphi); scoh = warpSum(scoh);
#pragma unroll
    for (int off = 16; off > 0; off >>= 1)
        mask |= __shfl_down_sync(0xffffffffu, mask, off);

    if (lane == 0) {
        sp[wid][0] = nv; sp[wid][1] = se;
        sp[wid][2] = ga0; sp[wid][3] = ga1; sp[wid][4] = ga2; sp[wid][5] = ga3;
        sp[wid][6] = sphi; sp[wid][7] = scoh;
        si[wid] = mask;
    }
    __syncthreads();
    if (wid == 0) {
        nv = sp[lane][0]; se = sp[lane][1];
        ga0 = sp[lane][2]; ga1 = sp[lane][3]; ga2 = sp[lane][4]; ga3 = sp[lane][5];
        sphi = sp[lane][6]; scoh = sp[lane][7];
        mask = si[lane];
        nv = warpSum(nv); se = warpSum(se);
        ga0 = warpSum(ga0); ga1 = warpSum(ga1); ga2 = warpSum(ga2); ga3 = warpSum(ga3);
        sphi = warpSum(sphi); scoh = warpSum(scoh);
#pragma unroll
        for (int off = 16; off > 0; off >>= 1)
            mask |= __shfl_down_sync(0xffffffffu, mask, off);

        if (lane == 0) {
            float nvalid = fmaxf(nv, 1.f);
            float g0 = ga0 / se, g1 = ga1 / se, g2 = ga2 / se, g3 = ga3 / se;
            float gm = fmaxf(fmaxf(g0, g1), fmaxf(g2, g3));
            float e0 = expf(g0 - gm), e1 = expf(g1 - gm);
            float e2 = expf(g2 - gm), e3 = expf(g3 - gm);
            float gs = e0 + e1 + e2 + e3;
            float* tail = out + (size_t)K * 8;
            tail[0] = e0 / gs; tail[1] = e1 / gs; tail[2] = e2 / gs; tail[3] = e3 / gs;
            float avg_phi = sphi / nvalid;
            float vert    = scoh / nvalid;
            float unique  = (float)__popc((unsigned)mask);
            tail[4] = fminf(1.f, avg_phi * (0.5f + 0.5f * unique / 4.f));
            tail[5] = vert;
        }
    }
}

// ---------------- launch ----------------
extern "C" void kernel_launch(void* const* d_in, const int* in_sizes, int n_in,
                              void* d_out, int out_size) {
    const float* state     = (const float*)d_in[0];
    const float* arch      = (const float*)d_in[1];
    const float* energy    = (const float*)d_in[2];
    const float* phi_local = (const float*)d_in[3];
    const float* surprise  = (const float*)d_in[4];
    const int*   seg_ids   = (const int*)d_in[5];
    // d_in[6] = n_clusters (device scalar) — K derived from out_size instead
    const float* W1 = (const float*)d_in[7];
    const float* b1 = (const float*)d_in[8];
    const float* W2 = (const float*)d_in[9];
    const float* b2 = (const float*)d_in[10];
    const float* V1 = (const float*)d_in[11];
    const float* c1 = (const float*)d_in[12];
    const float* V2 = (const float*)d_in[13];
    const float* c2 = (const float*)d_in[14];

    int N = in_sizes[2];                       // energy element count
    int K = (out_size - (A_DIM + 2)) / (A_DIM + 4);
    float* out = (float*)d_out;

    int gN = (N + 255) / 256;
    int gK = (K + 255) / 256;

    zeroK<<<gK, 256>>>(K);
    passA<<<gN, 256>>>(state, arch, energy, phi_local, surprise, seg_ids,
                       W1, b1, W2, b2, N);
    passC<<<gK, 256>>>(V1, c1, V2, c2, out, K);
    finalize<<<1, 1024>>>(out, K);
}